// round 9
// baseline (speedup 1.0000x reference)
#include <cuda_runtime.h>

#define DATA_DIM 512
#define BASIS_DIM 64
#define N_ROWS 2048
#define N_SPANS 61
#define THREADS 128
#define ROWS_TILE 32          // rows per CTA (lane = row)
#define DIMS_TILE 64          // dims per CTA (16 per warp)
#define N_RT (N_ROWS / ROWS_TILE)     // 64 row-tiles
#define N_CH (DATA_DIM / DIMS_TILE)   // 8 dim-chunks
#define X_PITCH 65            // smem pitch: conflict-free column reads

// cross-CTA reduction scratch (static zero-init; counter reset each use)
__device__ float g_part[N_RT][N_CH][ROWS_TILE];
__device__ int   g_cnt[N_RT];

// Clamped open-uniform knots: t[g] = clamp(g-3, 0, 61) / 61
__device__ __forceinline__ float knotf(int g) {
    int j = g - 3;
    j = max(0, min(N_SPANS, j));
    return (float)j / (float)N_SPANS;
}

// de Boor weights (polynomial extension) on span m, exact IEEE divides.
// 28 threads, once per CTA. Validated R4/R5/R8 (rel_err ~5e-7).
__device__ float4 deboor_weights(float xx, int m) {
    int k = m + 3;
    float left1  = xx - knotf(k);
    float left2  = xx - knotf(k - 1);
    float left3  = xx - knotf(k - 2);
    float right1 = knotf(k + 1) - xx;
    float right2 = knotf(k + 2) - xx;
    float right3 = knotf(k + 3) - xx;

    float N0 = 1.0f, N1, N2, N3, saved, temp;
    temp = N0 / (right1 + left1);
    N0 = right1 * temp;  N1 = left1 * temp;
    temp = N0 / (right1 + left2);
    N0 = right1 * temp;  saved = left2 * temp;
    temp = N1 / (right2 + left1);
    N1 = saved + right2 * temp;  N2 = left1 * temp;
    temp = N0 / (right1 + left3);
    N0 = right1 * temp;  saved = left3 * temp;
    temp = N1 / (right2 + left2);
    N1 = saved + right2 * temp;  saved = left2 * temp;
    temp = N2 / (right3 + left1);
    N2 = saved + right3 * temp;  N3 = left1 * temp;
    return make_float4(N0, N1, N2, N3);
}

__global__ void __launch_bounds__(THREADS)
bspline_tile_kernel(const float* __restrict__ x,
                    const float* __restrict__ A,
                    float* __restrict__ out) {
    __shared__ float  x_s[ROWS_TILE * X_PITCH];  // 32 x 64 tile, padded
    __shared__ float4 Wsm[7 * 4];                // boundary-class weight cubics
    __shared__ float  part[4 * 32];              // per-warp row partials

    const int tid  = threadIdx.x;
    const int wid  = tid >> 5;
    const int lane = tid & 31;
    const int ch   = blockIdx.x;   // dim chunk  [0,8)
    const int rt   = blockIdx.y;   // row tile   [0,64)

    // ---- stage 32x64 x-tile, coalesced float4 reads ----
    const float4* xg = reinterpret_cast<const float4*>(x);
    #pragma unroll
    for (int k = 0; k < 4; k++) {
        int q   = k * THREADS + tid;        // 0..511 float4 slots
        int row = q >> 4;                   // 16 float4 per row-segment
        int c4  = q & 15;
        float4 v = __ldg(&xg[(size_t)(rt * ROWS_TILE + row) * (DATA_DIM / 4)
                             + ch * (DIMS_TILE / 4) + c4]);
        float* d = &x_s[row * X_PITCH + c4 * 4];
        d[0] = v.x; d[1] = v.y; d[2] = v.z; d[3] = v.w;
    }

    // ---- build 7 boundary-class weight cubics (28 threads) ----
    // class c: m<3 -> m ; interior -> 3 ; m>57 -> m-54
    if (tid < 28) {
        int c = tid >> 2, j = tid & 3;
        int m_rep = (c < 3) ? c : ((c == 3) ? 30 : c + 54);
        float f[4];
        #pragma unroll
        for (int s = 0; s < 4; s++) {
            float xs = (float)(3 * m_rep + s) / (3.0f * (float)N_SPANS);
            float4 w = deboor_weights(xs, m_rep);
            f[s] = (j == 0) ? w.x : (j == 1) ? w.y : (j == 2) ? w.z : w.w;
        }
        // exact inverse Vandermonde at nodes {0, 1/3, 2/3, 1}
        float c0 = f[0];
        float c1 = -5.5f * f[0] +  9.0f * f[1] -  4.5f * f[2] +        f[3];
        float c2 =  9.0f * f[0] - 22.5f * f[1] + 18.0f * f[2] - 4.5f * f[3];
        float c3 = -4.5f * f[0] + 13.5f * f[1] - 13.5f * f[2] + 4.5f * f[3];
        Wsm[c * 4 + j] = make_float4(c0, c1, c2, c3);
    }
    __syncthreads();

    // ---- main: warp wid owns 16 dims; lane = row; A rows warp-uniform ----
    float acc = 0.0f;
    const int dbase = wid * 16;

    #pragma unroll 4
    for (int k = 0; k < 16; k++) {
        int dl = dbase + k;                 // local dim in tile
        int i  = ch * DIMS_TILE + dl;       // global dim
        float xx = x_s[lane * X_PITCH + dl];   // conflict-free column read

        float t = xx * (float)N_SPANS;
        int m = max(0, min(N_SPANS - 1, (int)t));
        float u = t - (float)m;
        int c = (m < 3) ? m : ((m > 57) ? m - 54 : 3);

        float4 p0 = Wsm[c * 4 + 0];
        float4 p1 = Wsm[c * 4 + 1];
        float4 p2 = Wsm[c * 4 + 2];
        float4 p3 = Wsm[c * 4 + 3];
        float w0 = fmaf(fmaf(fmaf(p0.w, u, p0.z), u, p0.y), u, p0.x);
        float w1 = fmaf(fmaf(fmaf(p1.w, u, p1.z), u, p1.y), u, p1.x);
        float w2 = fmaf(fmaf(fmaf(p2.w, u, p2.z), u, p2.y), u, p2.x);
        float w3 = fmaf(fmaf(fmaf(p3.w, u, p3.z), u, p3.y), u, p3.x);

        // warp-uniform A row i: gather touches ~2 lines per LDG
        const float* a = A + i * BASIS_DIM + m;
        acc = fmaf(w0, __ldg(a + 0),
              fmaf(w1, __ldg(a + 1),
              fmaf(w2, __ldg(a + 2),
              fmaf(w3, __ldg(a + 3), acc))));
    }

    // ---- CTA reduce across 4 warps (per row) ----
    part[wid * 32 + lane] = acc;
    __syncthreads();

    if (wid == 0) {
        float s = part[lane] + part[32 + lane] + part[64 + lane] + part[96 + lane];
        g_part[rt][ch][lane] = s;
        __threadfence();

        int last = 0;
        if (lane == 0) {
            int old = atomicAdd(&g_cnt[rt], 1);
            last = (old == N_CH - 1);
        }
        last = __shfl_sync(0xFFFFFFFFu, last, 0);

        if (last) {
            __threadfence();   // acquire: others' g_part writes visible
            float tot = 0.0f;
            #pragma unroll
            for (int j = 0; j < N_CH; j++)
                tot += __ldcg(&g_part[rt][j][lane]);   // L2, bypass stale L1
            out[rt * ROWS_TILE + lane] = 1.0f / (1.0f + __expf(-tot));
            if (lane == 0) g_cnt[rt] = 0;   // reset for next graph replay
        }
    }
}

extern "C" void kernel_launch(void* const* d_in, const int* in_sizes, int n_in,
                              void* d_out, int out_size) {
    // Disambiguate by element count: x is 2048*512, A is 512*64.
    const float* x = (const float*)d_in[0];
    const float* A = (const float*)d_in[1];
    if (n_in >= 2 && in_sizes[0] == DATA_DIM * BASIS_DIM &&
        in_sizes[1] == N_ROWS * DATA_DIM) {
        x = (const float*)d_in[1];
        A = (const float*)d_in[0];
    }
    float* out = (float*)d_out;  // [2048]

    dim3 grid(N_CH, N_RT);       // 8 x 64 = 512 CTAs
    bspline_tile_kernel<<<grid, THREADS>>>(x, A, out);
}